// round 6
// baseline (speedup 1.0000x reference)
#include <cuda_runtime.h>
#include <cstdint>

// GroupQuantizedLinear: y = (round(clip(W,-8,7)) * scale_per_group) @ x
// W: [8192, 8192] f32, scales: [8192, 64] f32 (group size 128), x: [8192] f32
// HBM-bound GEMV over 256 MB. 4 rows interleaved per block for MLP; occupancy
// raised to 5 blocks/SM (reg cap 51) to deepen in-flight DRAM loads.

static constexpr int IN_DIM  = 8192;
static constexpr int OUT_DIM = 8192;
static constexpr int GROUPS  = 64;      // group size = 128 channels = 32 float4
static constexpr int THREADS = 256;
static constexpr int ROWS    = 4;       // output rows per block, interleaved
static constexpr int VEC4    = IN_DIM / 4;          // 2048 float4 per row
static constexpr int ITERS   = VEC4 / THREADS;      // 8 float4 loads/thread/row
static constexpr int NWARP   = THREADS / 32;        // 8

__device__ __forceinline__ float qdot(float4 wv, float4 xv) {
    const float q0 = rintf(fminf(fmaxf(wv.x, -8.0f), 7.0f));
    const float q1 = rintf(fminf(fmaxf(wv.y, -8.0f), 7.0f));
    const float q2 = rintf(fminf(fmaxf(wv.z, -8.0f), 7.0f));
    const float q3 = rintf(fminf(fmaxf(wv.w, -8.0f), 7.0f));
    return q0 * xv.x + q1 * xv.y + q2 * xv.z + q3 * xv.w;
}

__global__ __launch_bounds__(THREADS, 5)
void gql_kernel(const float* __restrict__ x,
                const float* __restrict__ w,
                const float* __restrict__ scales,
                float* __restrict__ out)
{
    __shared__ float4 xs[VEC4];               // 32 KB: x staged once per block
    __shared__ float  ss[ROWS][GROUPS];       // 1 KB: scales for this block's rows
    __shared__ float  red[ROWS][NWARP];       // per-warp partials

    const int t    = threadIdx.x;
    const int row0 = blockIdx.x * ROWS;

    // Stage x (coalesced float4) and the 4 rows' scales
    const float4* x4 = reinterpret_cast<const float4*>(x);
    #pragma unroll
    for (int i = t; i < VEC4; i += THREADS) xs[i] = x4[i];
    if (t < ROWS * GROUPS) {
        const int r = t >> 6, g = t & 63;     // GROUPS = 64
        ss[r][g] = scales[(size_t)(row0 + r) * GROUPS + g];
    }
    __syncthreads();

    // One base pointer; row offsets become constant immediate offsets in LDG.
    const float4* wb = reinterpret_cast<const float4*>(w + (size_t)row0 * IN_DIM);

    float acc0 = 0.0f, acc1 = 0.0f, acc2 = 0.0f, acc3 = 0.0f;

    #pragma unroll
    for (int it = 0; it < ITERS; it++) {
        const int i4 = t + it * THREADS;      // float4 index within row
        // 4 independent streaming loads — high MLP, one xv reuse
        const float4 wv0 = __ldcs(wb + i4 + 0 * VEC4);
        const float4 wv1 = __ldcs(wb + i4 + 1 * VEC4);
        const float4 wv2 = __ldcs(wb + i4 + 2 * VEC4);
        const float4 wv3 = __ldcs(wb + i4 + 3 * VEC4);
        const float4 xv  = xs[i4];
        const int    g   = i4 >> 5;           // group = (4*i4)/128

        acc0 += ss[0][g] * qdot(wv0, xv);
        acc1 += ss[1][g] * qdot(wv1, xv);
        acc2 += ss[2][g] * qdot(wv2, xv);
        acc3 += ss[3][g] * qdot(wv3, xv);
    }

    // Warp-level reduction of all 4 accumulators
    #pragma unroll
    for (int off = 16; off; off >>= 1) {
        acc0 += __shfl_xor_sync(0xFFFFFFFFu, acc0, off);
        acc1 += __shfl_xor_sync(0xFFFFFFFFu, acc1, off);
        acc2 += __shfl_xor_sync(0xFFFFFFFFu, acc2, off);
        acc3 += __shfl_xor_sync(0xFFFFFFFFu, acc3, off);
    }
    const int wid = t >> 5, lane = t & 31;
    if (lane == 0) {
        red[0][wid] = acc0;
        red[1][wid] = acc1;
        red[2][wid] = acc2;
        red[3][wid] = acc3;
    }
    __syncthreads();

    // Warps 0..3 each reduce one row's NWARP partials; all 32 lanes active.
    if (wid < ROWS) {
        float v = (lane < NWARP) ? red[wid][lane] : 0.0f;
        #pragma unroll
        for (int off = NWARP / 2; off; off >>= 1)
            v += __shfl_xor_sync(0xFFFFFFFFu, v, off);
        if (lane == 0) out[row0 + wid] = v;
    }
}

extern "C" void kernel_launch(void* const* d_in, const int* in_sizes, int n_in,
                              void* d_out, int out_size)
{
    const float* x      = (const float*)d_in[0];   // [8192]
    const float* w      = (const float*)d_in[1];   // [8192*8192]
    const float* scales = (const float*)d_in[2];   // [8192*64]
    float* out = (float*)d_out;                    // [8192]

    gql_kernel<<<OUT_DIM / ROWS, THREADS>>>(x, w, scales, out);
}

// round 7
// speedup vs baseline: 1.0598x; 1.0598x over previous
#include <cuda_runtime.h>
#include <cstdint>

// GroupQuantizedLinear: y = (round(clip(W,-8,7)) * scale_per_group) @ x
// W: [8192, 8192] f32, scales: [8192, 64] f32 (group 128), x: [8192] f32
// HBM-bound GEMV over 256 MB. cp.async.bulk (TMA path) pipeline: weights are
// staged into a 2-stage smem ring via 4KB bulk copies (good DRAM page
// locality, in-flight depth decoupled from registers), compute reads smem.

static constexpr int IN_DIM  = 8192;
static constexpr int OUT_DIM = 8192;
static constexpr int GROUPS  = 64;          // group size = 128 channels
static constexpr int THREADS = 256;
static constexpr int ROWS    = 4;           // rows per block
static constexpr int CHUNK   = 1024;        // floats per row per chunk
static constexpr int NCHUNK  = IN_DIM / CHUNK;     // 8
static constexpr int STAGES  = 2;
static constexpr int CHUNK4  = CHUNK / 4;          // 256 float4 = THREADS
static constexpr int ROW_BYTES   = CHUNK * 4;      // 4096 per row per chunk
static constexpr int STAGE_BYTES = ROWS * ROW_BYTES; // 16384
static constexpr int NWARP   = THREADS / 32;       // 8

__device__ __forceinline__ uint32_t smem_u32(const void* p) {
    return (uint32_t)__cvta_generic_to_shared(p);
}

__device__ __forceinline__ void mbar_init(uint32_t a, uint32_t count) {
    asm volatile("mbarrier.init.shared.b64 [%0], %1;" :: "r"(a), "r"(count) : "memory");
}
__device__ __forceinline__ void mbar_expect_tx(uint32_t a, uint32_t bytes) {
    asm volatile("mbarrier.arrive.expect_tx.shared.b64 _, [%0], %1;"
                 :: "r"(a), "r"(bytes) : "memory");
}
__device__ __forceinline__ void mbar_arrive(uint32_t a) {
    asm volatile("mbarrier.arrive.shared.b64 _, [%0];" :: "r"(a) : "memory");
}
__device__ __forceinline__ void mbar_wait(uint32_t a, uint32_t parity) {
    asm volatile(
        "{\n\t.reg .pred P;\n\t"
        "WAIT_%=:\n\t"
        "mbarrier.try_wait.parity.acquire.cta.shared::cta.b64 P, [%0], %1, 0x989680;\n\t"
        "@!P bra WAIT_%=;\n\t}"
        :: "r"(a), "r"(parity) : "memory");
}
__device__ __forceinline__ void bulk_ld(uint32_t dst, const void* src,
                                        uint32_t bytes, uint32_t mbar) {
    asm volatile(
        "cp.async.bulk.shared::cluster.global.mbarrier::complete_tx::bytes "
        "[%0], [%1], %2, [%3];"
        :: "r"(dst), "l"(src), "r"(bytes), "r"(mbar) : "memory");
}

__device__ __forceinline__ float qdot(float4 wv, float4 xv) {
    const float q0 = rintf(fminf(fmaxf(wv.x, -8.0f), 7.0f));
    const float q1 = rintf(fminf(fmaxf(wv.y, -8.0f), 7.0f));
    const float q2 = rintf(fminf(fmaxf(wv.z, -8.0f), 7.0f));
    const float q3 = rintf(fminf(fmaxf(wv.w, -8.0f), 7.0f));
    return q0 * xv.x + q1 * xv.y + q2 * xv.z + q3 * xv.w;
}

__global__ __launch_bounds__(THREADS)
void gql_kernel(const float* __restrict__ x,
                const float* __restrict__ w,
                const float* __restrict__ scales,
                float* __restrict__ out)
{
    __shared__ __align__(128) float wbuf[STAGES][ROWS * CHUNK]; // 32 KB
    __shared__ float ss[ROWS][GROUPS];                          // 1 KB
    __shared__ float red[ROWS][NWARP];
    __shared__ __align__(8) unsigned long long mbar[2 * STAGES]; // full0,full1,empty0,empty1

    const int t    = threadIdx.x;
    const int row0 = blockIdx.x * ROWS;
    const uint32_t full0  = smem_u32(&mbar[0]);
    const uint32_t empty0 = smem_u32(&mbar[STAGES]);

    // Stage scales; init mbarriers
    if (t < ROWS * GROUPS) {
        const int r = t >> 6, g = t & 63;
        ss[r][g] = scales[(size_t)(row0 + r) * GROUPS + g];
    }
    if (t == 0) {
        #pragma unroll
        for (int s = 0; s < STAGES; s++) {
            mbar_init(full0  + 8u * s, 1);        // producer arrive + tx bytes
            mbar_init(empty0 + 8u * s, THREADS);  // all consumers release
        }
    }
    __syncthreads();

    const float* wrow = w + (size_t)row0 * IN_DIM;

    // Pre-issue first STAGES chunks
    if (t == 0) {
        #pragma unroll
        for (int c = 0; c < STAGES; c++) {
            const int s = c & 1;
            const uint32_t dst = smem_u32(&wbuf[s][0]);
            mbar_expect_tx(full0 + 8u * s, STAGE_BYTES);
            #pragma unroll
            for (int r = 0; r < ROWS; r++)
                bulk_ld(dst + r * ROW_BYTES,
                        wrow + (size_t)r * IN_DIM + c * CHUNK,
                        ROW_BYTES, full0 + 8u * s);
        }
    }

    const float4* x4 = reinterpret_cast<const float4*>(x);
    float acc0 = 0.0f, acc1 = 0.0f, acc2 = 0.0f, acc3 = 0.0f;

    #pragma unroll
    for (int c = 0; c < NCHUNK; c++) {
        const int s = c & 1, rr = c >> 1;
        mbar_wait(full0 + 8u * s, rr & 1);

        const float4* wb = reinterpret_cast<const float4*>(&wbuf[s][0]);
        const float4 wv0 = wb[0 * CHUNK4 + t];
        const float4 wv1 = wb[1 * CHUNK4 + t];
        const float4 wv2 = wb[2 * CHUNK4 + t];
        const float4 wv3 = wb[3 * CHUNK4 + t];
        const float4 xv  = __ldg(x4 + c * CHUNK4 + t);   // L1/L2-resident
        const int    g   = c * (CHUNK / 128) + (t >> 5); // global group index

        acc0 += ss[0][g] * qdot(wv0, xv);
        acc1 += ss[1][g] * qdot(wv1, xv);
        acc2 += ss[2][g] * qdot(wv2, xv);
        acc3 += ss[3][g] * qdot(wv3, xv);

        mbar_arrive(empty0 + 8u * s);

        // Producer refills this stage once all 256 consumers released it
        if (t == 0 && c + STAGES < NCHUNK) {
            mbar_wait(empty0 + 8u * s, rr & 1);
            const int cn = c + STAGES;
            const uint32_t dst = smem_u32(&wbuf[s][0]);
            mbar_expect_tx(full0 + 8u * s, STAGE_BYTES);
            #pragma unroll
            for (int r = 0; r < ROWS; r++)
                bulk_ld(dst + r * ROW_BYTES,
                        wrow + (size_t)r * IN_DIM + cn * CHUNK,
                        ROW_BYTES, full0 + 8u * s);
        }
    }

    // Warp-level reduction of all 4 accumulators
    #pragma unroll
    for (int off = 16; off; off >>= 1) {
        acc0 += __shfl_xor_sync(0xFFFFFFFFu, acc0, off);
        acc1 += __shfl_xor_sync(0xFFFFFFFFu, acc1, off);
        acc2 += __shfl_xor_sync(0xFFFFFFFFu, acc2, off);
        acc3 += __shfl_xor_sync(0xFFFFFFFFu, acc3, off);
    }
    const int wid = t >> 5, lane = t & 31;
    if (lane == 0) {
        red[0][wid] = acc0;
        red[1][wid] = acc1;
        red[2][wid] = acc2;
        red[3][wid] = acc3;
    }
    __syncthreads();

    if (wid < ROWS) {
        float v = (lane < NWARP) ? red[wid][lane] : 0.0f;
        #pragma unroll
        for (int off = NWARP / 2; off; off >>= 1)
            v += __shfl_xor_sync(0xFFFFFFFFu, v, off);
        if (lane == 0) out[row0 + wid] = v;
    }
}

extern "C" void kernel_launch(void* const* d_in, const int* in_sizes, int n_in,
                              void* d_out, int out_size)
{
    const float* x      = (const float*)d_in[0];   // [8192]
    const float* w      = (const float*)d_in[1];   // [8192*8192]
    const float* scales = (const float*)d_in[2];   // [8192*64]
    float* out = (float*)d_out;                    // [8192]

    gql_kernel<<<OUT_DIM / ROWS, THREADS>>>(x, w, scales, out);
}